// round 9
// baseline (speedup 1.0000x reference)
#include <cuda_runtime.h>
#include <math.h>
#include <stdint.h>

#define BB 4
#define TT 4096
#define DD 1024
#define NO 256      // 2*dv
#define NROW (BB*TT)
#define LN_EPS_F 1e-5f
#define LAMBDA_INIT 0.3555090675909693f
#define ATT_SCALE 0.0883883476483184405f   // 1/sqrt(128)

typedef unsigned long long u64;

// packed f32x2 helpers (sm_100+ PTX; SASS FFMA2/FADD2)
#define FFMA2(d, a, b) asm("fma.rn.f32x2 %0, %1, %2, %0;" : "+l"(d) : "l"(a), "l"(b))
#define FADD2(d, a)    asm("add.rn.f32x2 %0, %0, %1;"     : "+l"(d) : "l"(a))
#define PACK2(d, x)    asm("mov.b64 %0, {%1, %1};" : "=l"(d) : "r"(__float_as_uint(x)))
#define PACKAB(d, x, y) asm("mov.b64 %0, {%1, %2};" : "=l"(d) : "r"(__float_as_uint(x)), "r"(__float_as_uint(y)))
#define UNPACK2(lo, hi, v) do { unsigned _ul, _uh; \
    asm("mov.b64 {%0, %1}, %2;" : "=r"(_ul), "=r"(_uh) : "l"(v)); \
    (lo) = __uint_as_float(_ul); (hi) = __uint_as_float(_uh); } while (0)

// scratch (device globals: allocation-free rule)
__device__ float g_Q[NROW * NO];
__device__ float g_K[NROW * NO];
__device__ float g_V[NROW * NO];
__device__ float g_lambda;

// ---------------------------------------------------------------------------
// Kernel 1: uniform QKV GEMM.  C[16384 x 768] = X[16384 x 1024] @ {Wq|Wk|Wv}
// BM=128 BN=128 BK=16, 256 threads, 8x8 micro-tile, packed f32x2 FMAs.
// (proven round-7 version, unchanged)
// ---------------------------------------------------------------------------
__global__ __launch_bounds__(256) void qkv_gemm(
    const float* __restrict__ x,
    const float* __restrict__ Wq,
    const float* __restrict__ Wk,
    const float* __restrict__ Wv)
{
    __shared__ float Xs[16][132];   // [k][m], padded
    __shared__ float Ws[16][128];   // [k][n]

    const int nt  = blockIdx.x;          // 0..5
    const int mt  = blockIdx.y;          // 0..127
    const int mat = nt >> 1;             // 0=Q,1=K,2=V
    const int n0  = (nt & 1) * 128;
    const float* W = (mat == 0) ? Wq : ((mat == 1) ? Wk : Wv);
    float* Out     = (mat == 0) ? g_Q : ((mat == 1) ? g_K : g_V);

    const int m0  = mt * 128;
    const int tid = threadIdx.x;
    const int tx  = tid & 15;
    const int ty  = tid >> 4;

    const int xrow = tid >> 2;           // 0..63
    const int xkc  = tid & 3;            // 0..3
    const int wkr  = tid >> 5;           // 0..7
    const int wnc  = tid & 31;           // 0..31

    const float* xp0 = x + (size_t)(m0 + xrow) * DD + xkc * 4;
    const float* xp1 = x + (size_t)(m0 + xrow + 64) * DD + xkc * 4;
    const float* wp0 = W + (size_t)wkr * NO + n0 + wnc * 4;
    const float* wp1 = W + (size_t)(wkr + 8) * NO + n0 + wnc * 4;

    u64 c[4][8];
#pragma unroll
    for (int i = 0; i < 4; i++)
#pragma unroll
        for (int j = 0; j < 8; j++) c[i][j] = 0ull;

    float4 xr0 = *(const float4*)xp0;
    float4 xr1 = *(const float4*)xp1;
    float4 wr0 = *(const float4*)wp0;
    float4 wr1 = *(const float4*)wp1;

    for (int k0 = 0; k0 < DD; k0 += 16) {
        Xs[xkc * 4 + 0][xrow]      = xr0.x;
        Xs[xkc * 4 + 1][xrow]      = xr0.y;
        Xs[xkc * 4 + 2][xrow]      = xr0.z;
        Xs[xkc * 4 + 3][xrow]      = xr0.w;
        Xs[xkc * 4 + 0][xrow + 64] = xr1.x;
        Xs[xkc * 4 + 1][xrow + 64] = xr1.y;
        Xs[xkc * 4 + 2][xrow + 64] = xr1.z;
        Xs[xkc * 4 + 3][xrow + 64] = xr1.w;
        *(float4*)(&Ws[wkr][wnc * 4])     = wr0;
        *(float4*)(&Ws[wkr + 8][wnc * 4]) = wr1;
        __syncthreads();

        if (k0 + 16 < DD) {
            xr0 = *(const float4*)(xp0 + k0 + 16);
            xr1 = *(const float4*)(xp1 + k0 + 16);
            wr0 = *(const float4*)(wp0 + (size_t)(k0 + 16) * NO);
            wr1 = *(const float4*)(wp1 + (size_t)(k0 + 16) * NO);
        }

#pragma unroll
        for (int kk = 0; kk < 16; kk++) {
            ulonglong2 A0 = *(const ulonglong2*)(&Xs[kk][ty * 4]);
            ulonglong2 A1 = *(const ulonglong2*)(&Xs[kk][64 + ty * 4]);
            float4 b0 = *(const float4*)(&Ws[kk][tx * 4]);
            float4 b1 = *(const float4*)(&Ws[kk][64 + tx * 4]);
            u64 B[8];
            PACK2(B[0], b0.x); PACK2(B[1], b0.y); PACK2(B[2], b0.z); PACK2(B[3], b0.w);
            PACK2(B[4], b1.x); PACK2(B[5], b1.y); PACK2(B[6], b1.z); PACK2(B[7], b1.w);
#pragma unroll
            for (int j = 0; j < 8; j++) {
                FFMA2(c[0][j], A0.x, B[j]);
                FFMA2(c[1][j], A0.y, B[j]);
                FFMA2(c[2][j], A1.x, B[j]);
                FFMA2(c[3][j], A1.y, B[j]);
            }
        }
        __syncthreads();
    }

#pragma unroll
    for (int rp = 0; rp < 4; rp++) {
        const int r = (rp < 2) ? (ty * 4 + rp * 2) : (64 + ty * 4 + (rp - 2) * 2);
        float lo[8], hi[8];
#pragma unroll
        for (int j = 0; j < 8; j++) UNPACK2(lo[j], hi[j], c[rp][j]);
        float* o0 = Out + (size_t)(m0 + r) * NO + n0;
        float* o1 = o0 + NO;
        *(float4*)(o0 + tx * 4)      = make_float4(lo[0], lo[1], lo[2], lo[3]);
        *(float4*)(o0 + 64 + tx * 4) = make_float4(lo[4], lo[5], lo[6], lo[7]);
        *(float4*)(o1 + tx * 4)      = make_float4(hi[0], hi[1], hi[2], hi[3]);
        *(float4*)(o1 + 64 + tx * 4) = make_float4(hi[4], hi[5], hi[6], hi[7]);
    }
}

// ---------------------------------------------------------------------------
// Kernel 2: recompute the 64 state rows with the *_state weights.
// ---------------------------------------------------------------------------
__global__ __launch_bounds__(256) void state_fixup(
    const float* __restrict__ x,
    const float* __restrict__ Wqs,
    const float* __restrict__ Wks,
    const float* __restrict__ Wvs)
{
    __shared__ float xs[DD];
    const int id = blockIdx.x;             // 0..63
    const int b  = id >> 4;
    const int i  = id & 15;
    const int t  = (i < 8) ? i : (TT - 16 + i);
    const size_t row = (size_t)b * TT + t;
    const int tid = threadIdx.x;

    for (int d = tid; d < DD; d += 256) xs[d] = x[row * DD + d];
    __syncthreads();

    float aq = 0.f, ak = 0.f, av = 0.f;
    const int n = tid;
#pragma unroll 4
    for (int d = 0; d < DD; d++) {
        float xv = xs[d];
        aq += xv * Wqs[(size_t)d * NO + n];
        ak += xv * Wks[(size_t)d * NO + n];
        av += xv * Wvs[(size_t)d * NO + n];
    }
    g_Q[row * NO + n] = aq;
    g_K[row * NO + n] = ak;
    g_V[row * NO + n] = av;
}

// ---------------------------------------------------------------------------
// Kernel 3: lambda scalar
// ---------------------------------------------------------------------------
__global__ void lambda_kernel(const float* __restrict__ lq1,
                              const float* __restrict__ lq2,
                              const float* __restrict__ lk1,
                              const float* __restrict__ lk2)
{
    int lane = threadIdx.x;
    float s1 = 0.f, s2 = 0.f;
    for (int i = lane; i < 128; i += 32) {
        s1 += lq1[i] * lk1[i];
        s2 += lq2[i] * lk2[i];
    }
#pragma unroll
    for (int o = 16; o > 0; o >>= 1) {
        s1 += __shfl_xor_sync(0xffffffffu, s1, o);
        s2 += __shfl_xor_sync(0xffffffffu, s2, o);
    }
    if (lane == 0) g_lambda = expf(s1) - expf(s2) + LAMBDA_INIT;
}

// ---------------------------------------------------------------------------
// Kernel 4: fused differential causal attention + combine + LayerNorm.
// CTA = 256 threads (8 warps).  HEAD-SPLIT layout:
//   warps 0-3 -> head 1, rows (warp%4)*8 .. +7  (4 packed row-pairs)
//   warps 4-7 -> head 2, same rows
// Each warp loads only ITS head's K half (K crossbar traffic halved) and
// accumulates 8 rows over the full 256-dim V.  Heads are combined once per
// tile via a smem exchange (reusing the K staging region).
// Pair-balanced tiles (x, 127-x), no online max, smem-P broadcast.
// smem (float4 units): qp[2048] | ks[32*65] | vs[32*64] | ps[768]
// ---------------------------------------------------------------------------
#define SM_KS 2048
#define SM_VS (2048 + 32 * 65)
#define SM_PS (2048 + 32 * 65 + 32 * 64)
#define SM_TOTAL_F4 (2048 + 32 * 65 + 32 * 64 + 768)

__global__ __launch_bounds__(256, 2) void attn_kernel(
    float* __restrict__ out,
    const float* __restrict__ ln_gamma,
    const float* __restrict__ ln_beta)
{
    extern __shared__ float4 sm[];
    u64*    qp = (u64*)sm;              // [pair][dim 0..255] packed row-pairs
    float4* ks = sm + SM_KS;
    float4* vs = sm + SM_VS;
    float*  ps = (float*)(sm + SM_PS);  // [warp][key][12] (8 used)
    float*  ex = (float*)(sm + SM_KS);  // tile-end exchange, aliases ks

    const int b    = blockIdx.y;
    const int tid  = threadIdx.x;
    const int warp = tid >> 5;
    const int lane = tid & 31;
    const int h    = warp >> 2;          // 0 = head1, 1 = head2
    const int hw   = warp & 3;
    const size_t base = (size_t)b * TT;
    const float lamv = g_lambda;

    // LN params (used by head-1 warps in epilogue)
    float g[8], bt[8];
#pragma unroll
    for (int k = 0; k < 4; k++) {
        g[k]      = ln_gamma[lane * 4 + k];
        g[4 + k]  = ln_gamma[128 + lane * 4 + k];
        bt[k]     = ln_beta[lane * 4 + k];
        bt[4 + k] = ln_beta[128 + lane * 4 + k];
    }

    const int r0 = hw * 8;               // first of 8 rows for this warp
    float* psw = ps + warp * 32 * 12;
    // this warp's 4 row-pairs, its head's dim half
    const u64* q0 = qp + (hw * 4 + 0) * 256 + h * 128;
    const u64* q1 = q0 + 256;
    const u64* q2 = q0 + 512;
    const u64* q3 = q0 + 768;

#pragma unroll 1
    for (int pass = 0; pass < 2; pass++) {
        const int tile = pass ? (127 - blockIdx.x) : blockIdx.x;
        const int t0   = tile * 32;
        const int nch  = tile + 1;

        __syncthreads();   // previous pass fully done with smem

        // stage Q tile (32 rows) as packed row-pairs, pre-scaled by 1/sqrt(dk)
        for (int idx = tid; idx < 16 * 64; idx += 256) {
            int p  = idx >> 6;
            int dg = idx & 63;
            const float* r0p = g_Q + (base + t0 + 2 * p) * NO + dg * 4;
            float4 a = *(const float4*)r0p;
            float4 c = *(const float4*)(r0p + NO);
            u64 w0, w1, w2, w3;
            PACKAB(w0, a.x * ATT_SCALE, c.x * ATT_SCALE);
            PACKAB(w1, a.y * ATT_SCALE, c.y * ATT_SCALE);
            PACKAB(w2, a.z * ATT_SCALE, c.z * ATT_SCALE);
            PACKAB(w3, a.w * ATT_SCALE, c.w * ATT_SCALE);
            u64* dst = qp + p * 256 + dg * 4;
            dst[0] = w0; dst[1] = w1; dst[2] = w2; dst[3] = w3;
        }

        float l[8];                     // per-lane partial denominators (8 rows)
        u64 acc[8][4];
#pragma unroll
        for (int r = 0; r < 8; r++) {
            l[r] = 0.f;
            acc[r][0] = 0ull; acc[r][1] = 0ull;
            acc[r][2] = 0ull; acc[r][3] = 0ull;
        }

        for (int c = 0; c < nch; c++) {
            const int kb = c << 5;
            __syncthreads();
            // stage K/V chunk (32 keys)
            for (int idx = tid; idx < 32 * 64; idx += 256) {
                int key = idx >> 6;
                int d4  = idx & 63;
                size_t gr = (base + kb + key) * NO + d4 * 4;
                ks[key * 65 + d4] = *(const float4*)(g_K + gr);
                vs[key * 64 + d4] = *(const float4*)(g_V + gr);
            }
            __syncthreads();

            // scores: 4 row-pairs, ONE head (this warp's half of K)
            u64 s0e = 0ull, s0o = 0ull, s1e = 0ull, s1o = 0ull;
            u64 s2e = 0ull, s2o = 0ull, s3e = 0ull, s3o = 0ull;
            const float4* kp = ks + lane * 65 + h * 32;
#pragma unroll
            for (int gg = 0; gg < 32; gg++) {
                float4 kf = kp[gg];
                u64 k0, k1, k2, k3;
                PACK2(k0, kf.x); PACK2(k1, kf.y);
                PACK2(k2, kf.z); PACK2(k3, kf.w);
                ulonglong2 a0 = *(const ulonglong2*)(q0 + gg * 4);
                ulonglong2 a1 = *(const ulonglong2*)(q0 + gg * 4 + 2);
                FFMA2(s0e, k0, a0.x); FFMA2(s0o, k1, a0.y);
                FFMA2(s0e, k2, a1.x); FFMA2(s0o, k3, a1.y);
                ulonglong2 b0 = *(const ulonglong2*)(q1 + gg * 4);
                ulonglong2 b1 = *(const ulonglong2*)(q1 + gg * 4 + 2);
                FFMA2(s1e, k0, b0.x); FFMA2(s1o, k1, b0.y);
                FFMA2(s1e, k2, b1.x); FFMA2(s1o, k3, b1.y);
                ulonglong2 c0 = *(const ulonglong2*)(q2 + gg * 4);
                ulonglong2 c1 = *(const ulonglong2*)(q2 + gg * 4 + 2);
                FFMA2(s2e, k0, c0.x); FFMA2(s2o, k1, c0.y);
                FFMA2(s2e, k2, c1.x); FFMA2(s2o, k3, c1.y);
                ulonglong2 d0 = *(const ulonglong2*)(q3 + gg * 4);
                ulonglong2 d1 = *(const ulonglong2*)(q3 + gg * 4 + 2);
                FFMA2(s3e, k0, d0.x); FFMA2(s3o, k1, d0.y);
                FFMA2(s3e, k2, d1.x); FFMA2(s3o, k3, d1.y);
            }
            float sc[8];
            FADD2(s0e, s0o); UNPACK2(sc[0], sc[1], s0e);
            FADD2(s1e, s1o); UNPACK2(sc[2], sc[3], s1e);
            FADD2(s2e, s2o); UNPACK2(sc[4], sc[5], s2e);
            FADD2(s3e, s3o); UNPACK2(sc[6], sc[7], s3e);

            // p = exp(score), causal-masked; lane-local denominator; stash
            const int key = kb + lane;
            float pw[8];
#pragma unroll
            for (int ri = 0; ri < 8; ri++) {
                const int tg = t0 + r0 + ri;
                float p = (key <= tg) ? __expf(sc[ri]) : 0.f;
                l[ri] += p;
                pw[ri] = p;
            }
            float* pl = psw + lane * 12;
            *(float4*)(pl)     = make_float4(pw[0], pw[1], pw[2], pw[3]);
            *(float4*)(pl + 4) = make_float4(pw[4], pw[5], pw[6], pw[7]);
            __syncwarp();

            // P @ V: 8 rows share each V read
#pragma unroll 4
            for (int j = 0; j < 32; j++) {
                ulonglong2 v0 = *(const ulonglong2*)(vs + j * 64 + lane);
                ulonglong2 v1 = *(const ulonglong2*)(vs + j * 64 + 32 + lane);
                float4 pa = *(const float4*)(psw + j * 12);
                float4 pb = *(const float4*)(psw + j * 12 + 4);
                u64 w0, w1, w2, w3, w4, w5, w6, w7;
                PACK2(w0, pa.x); PACK2(w1, pa.y); PACK2(w2, pa.z); PACK2(w3, pa.w);
                PACK2(w4, pb.x); PACK2(w5, pb.y); PACK2(w6, pb.z); PACK2(w7, pb.w);
                FFMA2(acc[0][0], w0, v0.x); FFMA2(acc[0][1], w0, v0.y);
                FFMA2(acc[0][2], w0, v1.x); FFMA2(acc[0][3], w0, v1.y);
                FFMA2(acc[1][0], w1, v0.x); FFMA2(acc[1][1], w1, v0.y);
                FFMA2(acc[1][2], w1, v1.x); FFMA2(acc[1][3], w1, v1.y);
                FFMA2(acc[2][0], w2, v0.x); FFMA2(acc[2][1], w2, v0.y);
                FFMA2(acc[2][2], w2, v1.x); FFMA2(acc[2][3], w2, v1.y);
                FFMA2(acc[3][0], w3, v0.x); FFMA2(acc[3][1], w3, v0.y);
                FFMA2(acc[3][2], w3, v1.x); FFMA2(acc[3][3], w3, v1.y);
                FFMA2(acc[4][0], w4, v0.x); FFMA2(acc[4][1], w4, v0.y);
                FFMA2(acc[4][2], w4, v1.x); FFMA2(acc[4][3], w4, v1.y);
                FFMA2(acc[5][0], w5, v0.x); FFMA2(acc[5][1], w5, v0.y);
                FFMA2(acc[5][2], w5, v1.x); FFMA2(acc[5][3], w5, v1.y);
                FFMA2(acc[6][0], w6, v0.x); FFMA2(acc[6][1], w6, v0.y);
                FFMA2(acc[6][2], w6, v1.x); FFMA2(acc[6][3], w6, v1.y);
                FFMA2(acc[7][0], w7, v0.x); FFMA2(acc[7][1], w7, v0.y);
                FFMA2(acc[7][2], w7, v1.x); FFMA2(acc[7][3], w7, v1.y);
            }
            __syncwarp();
        }

        // reduce denominators once per tile
#pragma unroll
        for (int ri = 0; ri < 8; ri++) {
            float s = l[ri];
#pragma unroll
            for (int o = 16; o > 0; o >>= 1)
                s += __shfl_xor_sync(0xffffffffu, s, o);
            l[ri] = s;
        }

        // head-2 warps publish lambda/l2-scaled contributions to ex (32x256)
        if (h == 1) {
#pragma unroll
            for (int ri = 0; ri < 8; ri++) {
                const int row = r0 + ri;
                float i2 = lamv / l[ri];
                float* exr = ex + row * 256;
                float p0, p1, p2, p3;
                UNPACK2(p0, p1, acc[ri][0]); UNPACK2(p2, p3, acc[ri][1]);
                *(float4*)(exr + lane * 4) =
                    make_float4(p0 * i2, p1 * i2, p2 * i2, p3 * i2);
                UNPACK2(p0, p1, acc[ri][2]); UNPACK2(p2, p3, acc[ri][3]);
                *(float4*)(exr + 128 + lane * 4) =
                    make_float4(p0 * i2, p1 * i2, p2 * i2, p3 * i2);
            }
        }
        __syncthreads();

        // head-1 warps combine + LayerNorm + store
        if (h == 0) {
#pragma unroll
            for (int ri = 0; ri < 8; ri++) {
                const int row = r0 + ri;
                const int tg  = t0 + row;
                float i1 = 1.f / l[ri];
                const float* exr = ex + row * 256;
                float4 e0 = *(const float4*)(exr + lane * 4);
                float4 e1 = *(const float4*)(exr + 128 + lane * 4);
                float A[8];
                float p0, p1, p2, p3;
                UNPACK2(p0, p1, acc[ri][0]); UNPACK2(p2, p3, acc[ri][1]);
                A[0] = p0 * i1 - e0.x; A[1] = p1 * i1 - e0.y;
                A[2] = p2 * i1 - e0.z; A[3] = p3 * i1 - e0.w;
                UNPACK2(p0, p1, acc[ri][2]); UNPACK2(p2, p3, acc[ri][3]);
                A[4] = p0 * i1 - e1.x; A[5] = p1 * i1 - e1.y;
                A[6] = p2 * i1 - e1.z; A[7] = p3 * i1 - e1.w;

                float s = 0.f;
#pragma unroll
                for (int k = 0; k < 8; k++) s += A[k];
#pragma unroll
                for (int o = 16; o > 0; o >>= 1)
                    s += __shfl_xor_sync(0xffffffffu, s, o);
                float mu = s * (1.f / 256.f);

                float q = 0.f;
#pragma unroll
                for (int k = 0; k < 8; k++) q += (A[k] - mu) * (A[k] - mu);
#pragma unroll
                for (int o = 16; o > 0; o >>= 1)
                    q += __shfl_xor_sync(0xffffffffu, q, o);
                float var  = q * (1.f / 256.f);
                float rstd = rsqrtf(var + LN_EPS_F);

                float4 o0, o1;
                o0.x = (A[0] - mu) * rstd * g[0] + bt[0];
                o0.y = (A[1] - mu) * rstd * g[1] + bt[1];
                o0.z = (A[2] - mu) * rstd * g[2] + bt[2];
                o0.w = (A[3] - mu) * rstd * g[3] + bt[3];
                o1.x = (A[4] - mu) * rstd * g[4] + bt[4];
                o1.y = (A[5] - mu) * rstd * g[5] + bt[5];
                o1.z = (A[6] - mu) * rstd * g[6] + bt[6];
                o1.w = (A[7] - mu) * rstd * g[7] + bt[7];

                *(float4*)(out + (base + tg) * NO + lane * 4) = o0;
                *(float4*)(out + (base + tg) * NO + 128 + lane * 4) = o1;
            }
        }
    }
}

// ---------------------------------------------------------------------------
extern "C" void kernel_launch(void* const* d_in, const int* in_sizes, int n_in,
                              void* d_out, int out_size)
{
    const float* x   = (const float*)d_in[0];
    const float* Wq  = (const float*)d_in[1];
    const float* Wk  = (const float*)d_in[2];
    const float* Wv  = (const float*)d_in[3];
    const float* Wqs = (const float*)d_in[4];
    const float* Wks = (const float*)d_in[5];
    const float* Wvs = (const float*)d_in[6];
    const float* lq1 = (const float*)d_in[7];
    const float* lq2 = (const float*)d_in[8];
    const float* lk1 = (const float*)d_in[9];
    const float* lk2 = (const float*)d_in[10];
    const float* gam = (const float*)d_in[11];
    const float* bet = (const float*)d_in[12];

    qkv_gemm<<<dim3(6, 128), 256>>>(x, Wq, Wk, Wv);
    state_fixup<<<64, 256>>>(x, Wqs, Wks, Wvs);
    lambda_kernel<<<1, 32>>>(lq1, lq2, lk1, lk2);

    const int smem_bytes = SM_TOTAL_F4 * (int)sizeof(float4);
    cudaFuncSetAttribute(attn_kernel,
                         cudaFuncAttributeMaxDynamicSharedMemorySize, smem_bytes);
    attn_kernel<<<dim3(64, BB), 256, smem_bytes>>>((float*)d_out, gam, bet);
}